// round 13
// baseline (speedup 1.0000x reference)
#include <cuda_runtime.h>
#include <cuda_bf16.h>

// Shapes fixed by setup_inputs
#define BATCH 8
#define L 128
#define D 768
#define NF4 (D / 4)                  // 192 float4 per row
#define NROW (BATCH * L * L)         // 131072
#define PER_B (L * L)                // 16384
#define NQUAD (NROW / 4)             // 32768
#define GRID_ALL 592                 // 148 SMs x 4 blocks: exactly one wave
#define TOTW (GRID_ALL * 8)          // 4736 warps (quads/warp ~6.92, balanced)

// Device scratch (no allocations allowed)
__device__ float2   g_part[NROW * 8];   // per-(row, lane-group) partials, 8MB
__device__ unsigned g_keyS[NROW];
__device__ unsigned g_keyE[NROW];
__device__ float    g_lpS[512];
__device__ float    g_lpE[512];
__device__ int      g_hist[16 * 256];   // per-(head,batch) top-byte histogram
__device__ unsigned g_cnt = 0;          // barrier arrival counter (self-resetting)
__device__ unsigned g_rel = 0;          // barrier generation (monotonic)

// order-preserving float->uint encoding (monotonic over all floats)
__device__ __forceinline__ unsigned enc_f32(float f)
{
    unsigned u = __float_as_uint(f);
    return (u & 0x80000000u) ? ~u : (u | 0x80000000u);
}

// Grid-wide generation barrier. Valid because all GRID_ALL blocks are
// co-resident (4 blocks/SM guaranteed by __launch_bounds__(256,4) and
// modular block->SM placement). Self-resetting: g_cnt returns to 0 at each
// release; g_rel increments monotonically across uses AND graph replays.
__device__ __forceinline__ void grid_barrier()
{
    __syncthreads();
    if (threadIdx.x == 0) {
        __threadfence();                               // release my writes
        const unsigned gen = atomicAdd(&g_rel, 0u);    // read BEFORE arriving
        const unsigned old = atomicAdd(&g_cnt, 1u);
        if (old == GRID_ALL - 1u) {
            g_cnt = 0u;                                // reset before release
            __threadfence();
            atomicAdd(&g_rel, 1u);                     // release everyone
        } else {
            while (atomicAdd(&g_rel, 0u) == gen) { }
        }
    }
    __syncthreads();
    __threadfence();                                   // acquire
}

// ---------------------------------------------------------------------------
// ONE kernel, three phases separated by grid barriers.
// Phase M (all 592 blocks): streaming dual GEMV, per-lane float2 partials to
//   g_part (R10-proven mainloop: no cross-lane dep, no drain bubble).
// Phase A (blocks 0-511): 1 row/thread: reduce 8 lane-partials, bias, BCE
//   partials + encoded keys + smem top-byte histogram flushed sparsely.
// Phase B (blocks 0-15): exact k-th-largest radix select seeded by g_hist,
//   keys re-read from L2 per pass; block 16: loss reduction.
// out layout: [loss_S, loss_E, predict_S(131072), predict_E(131072)]
// ---------------------------------------------------------------------------
__global__ __launch_bounds__(256, 4) void k_all(
    const float* __restrict__ table,
    const float* __restrict__ W_S, const float* __restrict__ W_E,
    const int* __restrict__ labS, const int* __restrict__ labE,
    const float* __restrict__ bSp, const float* __restrict__ bEp,
    const int* __restrict__ amask,
    float* __restrict__ out)
{
    __shared__ float4 sWs[NF4];
    __shared__ float4 sWe[NF4];
    __shared__ int    sHistS[256];
    __shared__ int    sHistE[256];
    __shared__ float  rS[8], rE[8];

    const int tid  = threadIdx.x;
    const int blk  = blockIdx.x;
    const int warp = tid >> 5;
    const int lane = tid & 31;

    // ---- init: zero per-set histograms (pre-barrier-1) ----
    if (blk < 16) g_hist[blk * 256 + tid] = 0;

    for (int i = tid; i < NF4; i += 256) {
        sWs[i] = ((const float4*)W_S)[i];
        sWe[i] = ((const float4*)W_E)[i];
    }
    __syncthreads();

    // ======================= Phase M: mainloop =======================
    {
        const int sub = lane >> 3;       // row within quad (0..3)
        const int o   = lane & 7;        // float4 base offset (0..7)
        const int gw  = blk * 8 + warp;

        for (int q = gw; q < NQUAD; q += TOTW) {
            const long long row = (long long)q * 4 + sub;
            const float4* __restrict__ t = (const float4*)table + row * NF4;

            float s0 = 0.f, s1 = 0.f, e0 = 0.f, e1 = 0.f;
#pragma unroll
            for (int j = 0; j < 24; j += 2) {
                const int i0 = o + 8 * j;
                const int i1 = i0 + 8;
                const float4 v0 = __ldcs(&t[i0]);
                const float4 v1 = __ldcs(&t[i1]);
                const float4 a0 = sWs[i0], b0 = sWe[i0];
                const float4 a1 = sWs[i1], b1 = sWe[i1];
                s0 += v0.x * a0.x + v0.y * a0.y + v0.z * a0.z + v0.w * a0.w;
                e0 += v0.x * b0.x + v0.y * b0.y + v0.z * b0.z + v0.w * b0.w;
                s1 += v1.x * a1.x + v1.y * a1.y + v1.z * a1.z + v1.w * a1.w;
                e1 += v1.x * b1.x + v1.y * b1.y + v1.z * b1.z + v1.w * b1.w;
            }
            g_part[row * 8 + o] = make_float2(s0 + s1, e0 + e1);
        }
    }

    grid_barrier();

    // ======================= Phase A: prep =======================
    if (blk < 512) {
        const int row = blk * 256 + tid;       // 1 row per thread
        const int b   = blk >> 6;              // batch (64 blocks each)

        if (tid < 256) { sHistS[tid] = 0; sHistE[tid] = 0; }
        __syncthreads();

        const float4* __restrict__ p = (const float4*)(g_part + (long long)row * 8);
        float sS = 0.f, sE = 0.f;
#pragma unroll
        for (int k = 0; k < 4; k++) {
            const float4 v = p[k];      // (sS, sE, sS, sE)
            sS += v.x + v.z;
            sE += v.y + v.w;
        }

        const float lS = sS + bSp[0];
        const float lE = sE + bEp[0];
        const int   tS = labS[row];
        const int   tE = labE[row];
        const float w  = (tS >= 0) ? 1.0f : 0.0f;

        float bceS = w * (fmaxf(lS, 0.f) - lS * (float)tS + __logf(1.f + __expf(-fabsf(lS))));
        float bceE = w * (fmaxf(lE, 0.f) - lE * (float)tE + __logf(1.f + __expf(-fabsf(lE))));

        const unsigned kS = enc_f32(w / (1.f + __expf(-lS)));
        const unsigned kE = enc_f32(w / (1.f + __expf(-lE)));
        g_keyS[row] = kS;
        g_keyE[row] = kE;
        atomicAdd(&sHistS[kS >> 24], 1);
        atomicAdd(&sHistE[kE >> 24], 1);

        // deterministic block loss partials
#pragma unroll
        for (int off = 16; off; off >>= 1) {
            bceS += __shfl_xor_sync(0xFFFFFFFFu, bceS, off);
            bceE += __shfl_xor_sync(0xFFFFFFFFu, bceE, off);
        }
        if (lane == 0) { rS[warp] = bceS; rE[warp] = bceE; }
        __syncthreads();
        if (tid == 0) {
            float a = 0.f, b2 = 0.f;
#pragma unroll
            for (int k = 0; k < 8; k++) { a += rS[k]; b2 += rE[k]; }
            g_lpS[blk] = a;
            g_lpE[blk] = b2;
        }

        // sparse flush: one REDG per nonzero bin
        if (tid < 256) {
            const int cS = sHistS[tid];
            const int cE = sHistE[tid];
            if (cS) atomicAdd(&g_hist[b       * 256 + tid], cS);
            if (cE) atomicAdd(&g_hist[(8 + b) * 256 + tid], cE);
        }
    }

    grid_barrier();

    if (blk >= 17) return;

    // ======================= Phase B =======================
    if (blk == 16) {
        __shared__ float sA[256], sB[256];
        sA[tid] = g_lpS[tid] + g_lpS[tid + 256];
        sB[tid] = g_lpE[tid] + g_lpE[tid + 256];
        __syncthreads();
        for (int s = 128; s; s >>= 1) {
            if (tid < s) { sA[tid] += sA[tid + s]; sB[tid] += sB[tid + s]; }
            __syncthreads();
        }
        if (tid == 0) {
            out[0] = sA[0] / (float)NROW;
            out[1] = sB[0] / (float)NROW;
        }
        return;
    }

    const int b    = blk & 7;
    const int head = blk >> 3;
    const int set  = head * 8 + b;
    const unsigned* __restrict__ keys = (head ? g_keyE : g_keyS) + b * PER_B;

    __shared__ int      s_suf[256];
    __shared__ int      s_kk;
    __shared__ unsigned s_prefix, s_pmask;

    // span-pruning k, computed by warp 0
    if (warp == 0) {
        int m = amask[b * L + lane] + amask[b * L + 32 + lane]
              + amask[b * L + 64 + lane] + amask[b * L + 96 + lane];
#pragma unroll
        for (int off = 16; off; off >>= 1) m += __shfl_xor_sync(0xFFFFFFFFu, m, off);
        if (lane == 0) {
            const int mlen = m - 2;
            int len = (int)((float)mlen * 0.3f);   // trunc like .astype(int32)
            if (len < 5) len = 5;
            const int mlsq = mlen * mlen;
            if (len > mlsq) len = mlsq;
            if (len < 1) len = 1;
            if (len > PER_B) len = PER_B;
            s_kk = len;
            s_prefix = 0u;
            s_pmask  = 0u;
        }
    }
    // pass-3 histogram precomputed in phase A
    s_suf[tid] = g_hist[set * 256 + tid];
    __syncthreads();

    for (int pass = 3; pass >= 0; pass--) {
        const int shift = pass * 8;

        if (pass < 3) {
            s_suf[tid] = 0;
            __syncthreads();
            const unsigned pm = s_pmask;
            const unsigned pf = s_prefix;
#pragma unroll 8
            for (int i = 0; i < 64; i++) {
                const unsigned k = __ldcg(&keys[tid + 256 * i]);
                if ((k & pm) == pf)
                    atomicAdd(&s_suf[(k >> shift) & 0xFFu], 1);
            }
            __syncthreads();
        }

        // warp 0: suffix scan over 256 bins (8 bins/lane) + winner pick
        if (warp == 0) {
            const int k  = s_kk;
            const unsigned pf = s_prefix;
            const unsigned pm = s_pmask;
            int v[8], ls[8];
#pragma unroll
            for (int i = 0; i < 8; i++) v[i] = s_suf[lane * 8 + i];
            ls[7] = v[7];
#pragma unroll
            for (int i = 6; i >= 0; i--) ls[i] = ls[i + 1] + v[i];
            int T = ls[0];
            int S = T;
#pragma unroll
            for (int off = 1; off < 32; off <<= 1) {
                const int u = __shfl_down_sync(0xFFFFFFFFu, S, off);
                if (lane + off < 32) S += u;
            }
            const int E = S - T;   // sum over bins in higher lanes
#pragma unroll
            for (int i = 0; i < 8; i++) {
                const int suf = ls[i] + E;
                const int nxt = (i < 7) ? (ls[i + 1] + E) : E;
                if (suf >= k && nxt < k) {          // exactly one (lane,i) matches
                    s_prefix = pf | ((unsigned)(lane * 8 + i) << shift);
                    s_pmask  = pm | (0xFFu << shift);
                    s_kk     = k - nxt;
                }
            }
        }
        __syncthreads();
    }

    // s_prefix == encoded k-th largest key (bit-exact); key >= thr matches
    // the reference's pred >= topkth comparison
    const unsigned thr = s_prefix;
    float* __restrict__ o = out + 2 + head * NROW + b * PER_B;
#pragma unroll 8
    for (int i = 0; i < 64; i++) {
        const unsigned k = __ldcg(&keys[tid + 256 * i]);
        o[tid + 256 * i] = (k >= thr) ? 1.0f : 0.0f;
    }
}

// ---------------------------------------------------------------------------
extern "C" void kernel_launch(void* const* d_in, const int* in_sizes, int n_in,
                              void* d_out, int out_size)
{
    const float* table = (const float*)d_in[0];
    const int*   amask = (const int*)d_in[1];
    const int*   labS  = (const int*)d_in[2];
    const int*   labE  = (const int*)d_in[3];
    const float* W_S   = (const float*)d_in[4];
    const float* b_S   = (const float*)d_in[5];
    const float* W_E   = (const float*)d_in[6];
    const float* b_E   = (const float*)d_in[7];
    float* out = (float*)d_out;

    k_all<<<GRID_ALL, 256>>>(table, W_S, W_E, labS, labE, b_S, b_E, amask, out);
}

// round 14
// speedup vs baseline: 1.0803x; 1.0803x over previous
#include <cuda_runtime.h>
#include <cuda_bf16.h>

// Shapes fixed by setup_inputs
#define BATCH 8
#define L 128
#define D 768
#define NF4 (D / 4)                  // 192 float4 per row
#define NROW (BATCH * L * L)         // 131072
#define PER_B (L * L)                // 16384
#define NQUAD (NROW / 4)             // 32768
#define GRID1 592                    // 148 SMs x 4 blocks: one wave
#define TOTW (GRID1 * 8)             // 4736 warps (quads/warp ~6.92, balanced)

// Device scratch (no allocations allowed)
__device__ float2   g_part[NROW * 8];   // per-(row, lane-group) partials, 8MB
__device__ unsigned g_keyS[NROW];
__device__ unsigned g_keyE[NROW];
__device__ float    g_lpS[256];
__device__ float    g_lpE[256];
__device__ int      g_hist[16 * 256];   // per-(head,batch) top-byte histogram
__device__ int      g_arrive;           // fused-kernel arrival counter

// order-preserving float->uint encoding (monotonic over all floats)
__device__ __forceinline__ unsigned enc_f32(float f)
{
    unsigned u = __float_as_uint(f);
    return (u & 0x80000000u) ? ~u : (u | 0x80000000u);
}

// ---------------------------------------------------------------------------
// K1: pure streaming dual GEMV (proven 69.7us, 74% DRAM, 39 regs).
// Warp covers 4 rows (8 lanes/row, 24 float4/lane). Each lane stores its own
// (sS,sE) partial as one 8B float2 -> no cross-lane dep, no drain bubble.
// Blocks 0-15 zero g_hist; block 16 zeroes g_arrive.
// ---------------------------------------------------------------------------
__global__ __launch_bounds__(256) void k_main(
    const float* __restrict__ table,
    const float* __restrict__ W_S,
    const float* __restrict__ W_E)
{
    __shared__ float4 sWs[NF4];
    __shared__ float4 sWe[NF4];

    if (blockIdx.x < 16) g_hist[blockIdx.x * 256 + threadIdx.x] = 0;
    if (blockIdx.x == 16 && threadIdx.x == 0) g_arrive = 0;

    for (int i = threadIdx.x; i < NF4; i += 256) {
        sWs[i] = ((const float4*)W_S)[i];
        sWe[i] = ((const float4*)W_E)[i];
    }
    __syncthreads();

    const int warp = threadIdx.x >> 5;
    const int lane = threadIdx.x & 31;
    const int sub  = lane >> 3;       // row within quad (0..3)
    const int o    = lane & 7;        // float4 base offset (0..7)
    const int gw   = blockIdx.x * 8 + warp;

    for (int q = gw; q < NQUAD; q += TOTW) {
        const long long row = (long long)q * 4 + sub;
        const float4* __restrict__ t = (const float4*)table + row * NF4;

        float s0 = 0.f, s1 = 0.f, e0 = 0.f, e1 = 0.f;
#pragma unroll
        for (int j = 0; j < 24; j += 2) {
            const int i0 = o + 8 * j;
            const int i1 = i0 + 8;
            const float4 v0 = __ldcs(&t[i0]);
            const float4 v1 = __ldcs(&t[i1]);
            const float4 a0 = sWs[i0], b0 = sWe[i0];
            const float4 a1 = sWs[i1], b1 = sWe[i1];
            s0 += v0.x * a0.x + v0.y * a0.y + v0.z * a0.z + v0.w * a0.w;
            e0 += v0.x * b0.x + v0.y * b0.y + v0.z * b0.z + v0.w * b0.w;
            s1 += v1.x * a1.x + v1.y * a1.y + v1.z * a1.z + v1.w * a1.w;
            e1 += v1.x * b1.x + v1.y * b1.y + v1.z * b1.z + v1.w * b1.w;
        }
        g_part[row * 8 + o] = make_float2(s0 + s1, e0 + e1);
    }
}

// ---------------------------------------------------------------------------
// K2 (fused prep + select): 256 blocks x 512 threads, all resident in one
// wave so the in-kernel arrival sync cannot deadlock. NO register key cache
// (keys re-read from L2 via __ldcg in phase B) -> low regs, better phase-A
// occupancy.
// Phase A (all blocks): reduce lane-partials, bias, BCE partials + encoded
//   keys; smem top-byte histogram flushed sparsely to g_hist.
// Sync: global arrival counter (release/acquire via threadfence).
// Phase B (blocks 0-15): exact k-th largest radix select seeded by g_hist
//   + predict-mask write. Block 16: final loss reduction.
// out layout: [loss_S, loss_E, predict_S(131072), predict_E(131072)]
// ---------------------------------------------------------------------------
#define SELT 512
#define KPT  (PER_B / SELT)          // 32

__global__ __launch_bounds__(SELT) void k_fuse(
    const int* __restrict__ labS, const int* __restrict__ labE,
    const float* __restrict__ bSp, const float* __restrict__ bEp,
    const int* __restrict__ amask,
    float* __restrict__ out)
{
    const int tid  = threadIdx.x;
    const int lane = tid & 31;
    const int warp = tid >> 5;

    // ======================== Phase A: prep ========================
    {
        const int i = blockIdx.x * 512 + tid;      // row id
        const int b = blockIdx.x >> 5;             // batch (32 blocks each)

        __shared__ int histS[256];
        __shared__ int histE[256];
        if (tid < 256) { histS[tid] = 0; histE[tid] = 0; }
        __syncthreads();

        const float4* __restrict__ p = (const float4*)(g_part + (long long)i * 8);
        float sS = 0.f, sE = 0.f;
#pragma unroll
        for (int k = 0; k < 4; k++) {
            const float4 v = p[k];      // (sS, sE, sS, sE)
            sS += v.x + v.z;
            sE += v.y + v.w;
        }

        const float lS = sS + bSp[0];
        const float lE = sE + bEp[0];
        const int   tS = labS[i];
        const int   tE = labE[i];
        const float w  = (tS >= 0) ? 1.0f : 0.0f;

        float bceS = w * (fmaxf(lS, 0.f) - lS * (float)tS + __logf(1.f + __expf(-fabsf(lS))));
        float bceE = w * (fmaxf(lE, 0.f) - lE * (float)tE + __logf(1.f + __expf(-fabsf(lE))));

        const unsigned kS = enc_f32(w / (1.f + __expf(-lS)));
        const unsigned kE = enc_f32(w / (1.f + __expf(-lE)));
        g_keyS[i] = kS;
        g_keyE[i] = kE;
        atomicAdd(&histS[kS >> 24], 1);
        atomicAdd(&histE[kE >> 24], 1);

        __shared__ float rS[16], rE[16];
#pragma unroll
        for (int off = 16; off; off >>= 1) {
            bceS += __shfl_xor_sync(0xFFFFFFFFu, bceS, off);
            bceE += __shfl_xor_sync(0xFFFFFFFFu, bceE, off);
        }
        if (lane == 0) { rS[warp] = bceS; rE[warp] = bceE; }
        __syncthreads();
        if (tid == 0) {
            float a = 0.f, b2 = 0.f;
#pragma unroll
            for (int k = 0; k < 16; k++) { a += rS[k]; b2 += rE[k]; }
            g_lpS[blockIdx.x] = a;
            g_lpE[blockIdx.x] = b2;
        }

        // sparse flush: one REDG per nonzero bin
        if (tid < 256) {
            const int cS = histS[tid];
            const int cE = histE[tid];
            if (cS) atomicAdd(&g_hist[b       * 256 + tid], cS);
            if (cE) atomicAdd(&g_hist[(8 + b) * 256 + tid], cE);
        }
    }

    // ======================== arrival sync ========================
    __threadfence();          // release all phase-A writes
    __syncthreads();
    if (tid == 0) atomicAdd(&g_arrive, 1);

    if (blockIdx.x >= 17) return;

    if (tid == 0) {
        while (atomicAdd(&g_arrive, 0) < 256) { }   // spin (all blocks resident)
    }
    __syncthreads();
    __threadfence();          // acquire

    // ======================== Phase B ========================
    if (blockIdx.x == 16) {
        __shared__ float sA[256], sB[256];
        if (tid < 256) { sA[tid] = g_lpS[tid]; sB[tid] = g_lpE[tid]; }
        __syncthreads();
        for (int s = 128; s; s >>= 1) {
            if (tid < s) { sA[tid] += sA[tid + s]; sB[tid] += sB[tid + s]; }
            __syncthreads();
        }
        if (tid == 0) {
            out[0] = sA[0] / (float)NROW;
            out[1] = sB[0] / (float)NROW;
        }
        return;
    }

    const int b    = blockIdx.x & 7;
    const int head = blockIdx.x >> 3;
    const int set  = head * 8 + b;
    const unsigned* __restrict__ keys = (head ? g_keyE : g_keyS) + b * PER_B;

    __shared__ int      s_suf[256];
    __shared__ int      s_kk;
    __shared__ unsigned s_prefix, s_pmask;

    // span-pruning k, computed by warp 0
    if (warp == 0) {
        int m = amask[b * L + lane] + amask[b * L + 32 + lane]
              + amask[b * L + 64 + lane] + amask[b * L + 96 + lane];
#pragma unroll
        for (int off = 16; off; off >>= 1) m += __shfl_xor_sync(0xFFFFFFFFu, m, off);
        if (lane == 0) {
            const int mlen = m - 2;
            int len = (int)((float)mlen * 0.3f);   // trunc like .astype(int32)
            if (len < 5) len = 5;
            const int mlsq = mlen * mlen;
            if (len > mlsq) len = mlsq;
            if (len < 1) len = 1;
            if (len > PER_B) len = PER_B;
            s_kk = len;
            s_prefix = 0u;
            s_pmask  = 0u;
        }
    }
    // pass-3 histogram precomputed in phase A
    if (tid < 256) s_suf[tid] = g_hist[set * 256 + tid];
    __syncthreads();

    for (int pass = 3; pass >= 0; pass--) {
        const int shift = pass * 8;

        if (pass < 3) {
            if (tid < 256) s_suf[tid] = 0;
            __syncthreads();
            const unsigned pm = s_pmask;
            const unsigned pf = s_prefix;
#pragma unroll 8
            for (int i = 0; i < KPT; i++) {
                const unsigned k = __ldcg(&keys[tid + SELT * i]);
                if ((k & pm) == pf)
                    atomicAdd(&s_suf[(k >> shift) & 0xFFu], 1);
            }
            __syncthreads();
        }

        // warp 0: suffix scan over 256 bins (8 bins/lane) + winner pick
        if (warp == 0) {
            const int k  = s_kk;
            const unsigned pf = s_prefix;
            const unsigned pm = s_pmask;
            int v[8], ls[8];
#pragma unroll
            for (int i = 0; i < 8; i++) v[i] = s_suf[lane * 8 + i];
            ls[7] = v[7];
#pragma unroll
            for (int i = 6; i >= 0; i--) ls[i] = ls[i + 1] + v[i];
            int T = ls[0];
            int S = T;
#pragma unroll
            for (int off = 1; off < 32; off <<= 1) {
                const int u = __shfl_down_sync(0xFFFFFFFFu, S, off);
                if (lane + off < 32) S += u;
            }
            const int E = S - T;   // sum over bins in higher lanes
#pragma unroll
            for (int i = 0; i < 8; i++) {
                const int suf = ls[i] + E;
                const int nxt = (i < 7) ? (ls[i + 1] + E) : E;
                if (suf >= k && nxt < k) {          // exactly one (lane,i) matches
                    s_prefix = pf | ((unsigned)(lane * 8 + i) << shift);
                    s_pmask  = pm | (0xFFu << shift);
                    s_kk     = k - nxt;
                }
            }
        }
        __syncthreads();
    }

    // s_prefix == encoded k-th largest key (bit-exact); key >= thr matches
    // the reference's pred >= topkth comparison
    const unsigned thr = s_prefix;
    float* __restrict__ o = out + 2 + head * NROW + b * PER_B;
#pragma unroll 8
    for (int i = 0; i < KPT; i++) {
        const unsigned k = __ldcg(&keys[tid + SELT * i]);
        o[tid + SELT * i] = (k >= thr) ? 1.0f : 0.0f;
    }
}

// ---------------------------------------------------------------------------
extern "C" void kernel_launch(void* const* d_in, const int* in_sizes, int n_in,
                              void* d_out, int out_size)
{
    const float* table = (const float*)d_in[0];
    const int*   amask = (const int*)d_in[1];
    const int*   labS  = (const int*)d_in[2];
    const int*   labE  = (const int*)d_in[3];
    const float* W_S   = (const float*)d_in[4];
    const float* b_S   = (const float*)d_in[5];
    const float* W_E   = (const float*)d_in[6];
    const float* b_E   = (const float*)d_in[7];
    float* out = (float*)d_out;

    k_main<<<GRID1, 256>>>(table, W_S, W_E);
    k_fuse<<<256, SELT>>>(labS, labE, b_S, b_E, amask, out);
}

// round 15
// speedup vs baseline: 1.1606x; 1.0743x over previous
#include <cuda_runtime.h>
#include <cuda_bf16.h>

// Shapes fixed by setup_inputs
#define BATCH 8
#define L 128
#define D 768
#define NF4 (D / 4)                  // 192 float4 per row
#define NROW (BATCH * L * L)         // 131072
#define PER_B (L * L)                // 16384
#define NQUAD (NROW / 4)             // 32768
#define GRID1 592                    // 148 SMs x 4 blocks: one wave
#define TOTW (GRID1 * 8)             // 4736 warps (quads/warp ~6.92, balanced)

// Device scratch (no allocations allowed)
__device__ float2   g_part[NROW * 8];   // per-(row, lane-group) partials, 8MB
__device__ unsigned g_keyS[NROW];
__device__ unsigned g_keyE[NROW];
__device__ float    g_lpS[256];
__device__ float    g_lpE[256];
__device__ int      g_hist[16 * 256];   // per-(head,batch) top-byte histogram
__device__ int      g_arrive;           // fused-kernel arrival counter

// order-preserving float->uint encoding (monotonic over all floats)
__device__ __forceinline__ unsigned enc_f32(float f)
{
    unsigned u = __float_as_uint(f);
    return (u & 0x80000000u) ? ~u : (u | 0x80000000u);
}

// ---------------------------------------------------------------------------
// K1: pure streaming dual GEMV (proven 69.7us, 74% DRAM, 39 regs).
// Warp covers 4 rows (8 lanes/row, 24 float4/lane). Each lane stores its own
// (sS,sE) partial as one 8B float2 -> no cross-lane dep, no drain bubble.
// Blocks 0-15 zero g_hist; block 16 zeroes g_arrive.
// ---------------------------------------------------------------------------
__global__ __launch_bounds__(256) void k_main(
    const float* __restrict__ table,
    const float* __restrict__ W_S,
    const float* __restrict__ W_E)
{
    __shared__ float4 sWs[NF4];
    __shared__ float4 sWe[NF4];

    if (blockIdx.x < 16) g_hist[blockIdx.x * 256 + threadIdx.x] = 0;
    if (blockIdx.x == 16 && threadIdx.x == 0) g_arrive = 0;

    for (int i = threadIdx.x; i < NF4; i += 256) {
        sWs[i] = ((const float4*)W_S)[i];
        sWe[i] = ((const float4*)W_E)[i];
    }
    __syncthreads();

    const int warp = threadIdx.x >> 5;
    const int lane = threadIdx.x & 31;
    const int sub  = lane >> 3;       // row within quad (0..3)
    const int o    = lane & 7;        // float4 base offset (0..7)
    const int gw   = blockIdx.x * 8 + warp;

    for (int q = gw; q < NQUAD; q += TOTW) {
        const long long row = (long long)q * 4 + sub;
        const float4* __restrict__ t = (const float4*)table + row * NF4;

        float s0 = 0.f, s1 = 0.f, e0 = 0.f, e1 = 0.f;
#pragma unroll
        for (int j = 0; j < 24; j += 2) {
            const int i0 = o + 8 * j;
            const int i1 = i0 + 8;
            const float4 v0 = __ldcs(&t[i0]);
            const float4 v1 = __ldcs(&t[i1]);
            const float4 a0 = sWs[i0], b0 = sWe[i0];
            const float4 a1 = sWs[i1], b1 = sWe[i1];
            s0 += v0.x * a0.x + v0.y * a0.y + v0.z * a0.z + v0.w * a0.w;
            e0 += v0.x * b0.x + v0.y * b0.y + v0.z * b0.z + v0.w * b0.w;
            s1 += v1.x * a1.x + v1.y * a1.y + v1.z * a1.z + v1.w * a1.w;
            e1 += v1.x * b1.x + v1.y * b1.y + v1.z * b1.z + v1.w * b1.w;
        }
        g_part[row * 8 + o] = make_float2(s0 + s1, e0 + e1);
    }
}

// ---------------------------------------------------------------------------
// K2 (fused prep + select, PDL secondary): 256 blocks x 512 threads, all
// resident in one wave so the arrival sync cannot deadlock. Launched with
// programmatic stream serialization: blocks start during k_main's drain,
// run the k_main-independent preamble, then cudaGridDependencySynchronize()
// before touching g_part / g_hist.
// Phase A (all blocks): reduce lane-partials, bias, BCE partials + encoded
//   keys (register key cache); smem top-byte histogram flushed sparsely.
// Phase B (blocks 0-15): exact k-th largest radix select seeded by g_hist
//   + predict-mask write. Block 16: final loss reduction.
// out layout: [loss_S, loss_E, predict_S(131072), predict_E(131072)]
// ---------------------------------------------------------------------------
#define SELT 512
#define KPT  (PER_B / SELT)          // 32

__global__ __launch_bounds__(SELT) void k_fuse(
    const int* __restrict__ labS, const int* __restrict__ labE,
    const float* __restrict__ bSp, const float* __restrict__ bEp,
    const int* __restrict__ amask,
    float* __restrict__ out)
{
    const int tid  = threadIdx.x;
    const int lane = tid & 31;
    const int warp = tid >> 5;

    // ======================== Phase A: prep ========================
    {
        const int i = blockIdx.x * 512 + tid;      // row id
        const int b = blockIdx.x >> 5;             // batch (32 blocks each)

        __shared__ int histS[256];
        __shared__ int histE[256];
        if (tid < 256) { histS[tid] = 0; histE[tid] = 0; }

        // k_main-independent preamble: labels + bias (overlaps k_main drain)
        const int   tS = labS[i];
        const int   tE = labE[i];
        const float bS = bSp[0];
        const float bE = bEp[0];
        __syncthreads();

        // wait for k_main completion (g_part + g_hist zero + g_arrive zero)
        cudaGridDependencySynchronize();

        const float4* __restrict__ p = (const float4*)(g_part + (long long)i * 8);
        float sS = 0.f, sE = 0.f;
#pragma unroll
        for (int k = 0; k < 4; k++) {
            const float4 v = p[k];      // (sS, sE, sS, sE)
            sS += v.x + v.z;
            sE += v.y + v.w;
        }

        const float lS = sS + bS;
        const float lE = sE + bE;
        const float w  = (tS >= 0) ? 1.0f : 0.0f;

        float bceS = w * (fmaxf(lS, 0.f) - lS * (float)tS + __logf(1.f + __expf(-fabsf(lS))));
        float bceE = w * (fmaxf(lE, 0.f) - lE * (float)tE + __logf(1.f + __expf(-fabsf(lE))));

        const unsigned kS = enc_f32(w / (1.f + __expf(-lS)));
        const unsigned kE = enc_f32(w / (1.f + __expf(-lE)));
        g_keyS[i] = kS;
        g_keyE[i] = kE;
        atomicAdd(&histS[kS >> 24], 1);
        atomicAdd(&histE[kE >> 24], 1);

        __shared__ float rS[16], rE[16];
#pragma unroll
        for (int off = 16; off; off >>= 1) {
            bceS += __shfl_xor_sync(0xFFFFFFFFu, bceS, off);
            bceE += __shfl_xor_sync(0xFFFFFFFFu, bceE, off);
        }
        if (lane == 0) { rS[warp] = bceS; rE[warp] = bceE; }
        __syncthreads();
        if (tid == 0) {
            float a = 0.f, b2 = 0.f;
#pragma unroll
            for (int k = 0; k < 16; k++) { a += rS[k]; b2 += rE[k]; }
            g_lpS[blockIdx.x] = a;
            g_lpE[blockIdx.x] = b2;
        }

        // sparse flush: one REDG per nonzero bin
        if (tid < 256) {
            const int cS = histS[tid];
            const int cE = histE[tid];
            if (cS) atomicAdd(&g_hist[b       * 256 + tid], cS);
            if (cE) atomicAdd(&g_hist[(8 + b) * 256 + tid], cE);
        }
    }

    // ======================== arrival sync ========================
    __threadfence();          // release all phase-A writes
    __syncthreads();
    if (tid == 0) atomicAdd(&g_arrive, 1);

    if (blockIdx.x >= 17) return;

    if (tid == 0) {
        while (atomicAdd(&g_arrive, 0) < 256) { }   // spin (all blocks resident)
    }
    __syncthreads();
    __threadfence();          // acquire

    // ======================== Phase B ========================
    if (blockIdx.x == 16) {
        __shared__ float sA[256], sB[256];
        if (tid < 256) { sA[tid] = g_lpS[tid]; sB[tid] = g_lpE[tid]; }
        __syncthreads();
        for (int s = 128; s; s >>= 1) {
            if (tid < s) { sA[tid] += sA[tid + s]; sB[tid] += sB[tid + s]; }
            __syncthreads();
        }
        if (tid == 0) {
            out[0] = sA[0] / (float)NROW;
            out[1] = sB[0] / (float)NROW;
        }
        return;
    }

    const int b    = blockIdx.x & 7;
    const int head = blockIdx.x >> 3;
    const int set  = head * 8 + b;
    const unsigned* __restrict__ keys = (head ? g_keyE : g_keyS) + b * PER_B;

    unsigned key[KPT];
#pragma unroll
    for (int i = 0; i < KPT; i++) key[i] = keys[tid + SELT * i];

    __shared__ int      s_suf[256];
    __shared__ int      s_kk;
    __shared__ unsigned s_prefix, s_pmask;

    // span-pruning k, computed by warp 0
    if (warp == 0) {
        int m = amask[b * L + lane] + amask[b * L + 32 + lane]
              + amask[b * L + 64 + lane] + amask[b * L + 96 + lane];
#pragma unroll
        for (int off = 16; off; off >>= 1) m += __shfl_xor_sync(0xFFFFFFFFu, m, off);
        if (lane == 0) {
            const int mlen = m - 2;
            int len = (int)((float)mlen * 0.3f);   // trunc like .astype(int32)
            if (len < 5) len = 5;
            const int mlsq = mlen * mlen;
            if (len > mlsq) len = mlsq;
            if (len < 1) len = 1;
            if (len > PER_B) len = PER_B;
            s_kk = len;
            s_prefix = 0u;
            s_pmask  = 0u;
        }
    }
    // pass-3 histogram precomputed in phase A
    if (tid < 256) s_suf[tid] = g_hist[set * 256 + tid];
    __syncthreads();

    for (int pass = 3; pass >= 0; pass--) {
        const int shift = pass * 8;

        if (pass < 3) {
            if (tid < 256) s_suf[tid] = 0;
            __syncthreads();
            const unsigned pm = s_pmask;
            const unsigned pf = s_prefix;
#pragma unroll
            for (int i = 0; i < KPT; i++) {
                if ((key[i] & pm) == pf)
                    atomicAdd(&s_suf[(key[i] >> shift) & 0xFFu], 1);
            }
            __syncthreads();
        }

        // warp 0: suffix scan over 256 bins (8 bins/lane) + winner pick
        if (warp == 0) {
            const int k  = s_kk;
            const unsigned pf = s_prefix;
            const unsigned pm = s_pmask;
            int v[8], ls[8];
#pragma unroll
            for (int i = 0; i < 8; i++) v[i] = s_suf[lane * 8 + i];
            ls[7] = v[7];
#pragma unroll
            for (int i = 6; i >= 0; i--) ls[i] = ls[i + 1] + v[i];
            int T = ls[0];
            int S = T;
#pragma unroll
            for (int off = 1; off < 32; off <<= 1) {
                const int u = __shfl_down_sync(0xFFFFFFFFu, S, off);
                if (lane + off < 32) S += u;
            }
            const int E = S - T;   // sum over bins in higher lanes
#pragma unroll
            for (int i = 0; i < 8; i++) {
                const int suf = ls[i] + E;
                const int nxt = (i < 7) ? (ls[i + 1] + E) : E;
                if (suf >= k && nxt < k) {          // exactly one (lane,i) matches
                    s_prefix = pf | ((unsigned)(lane * 8 + i) << shift);
                    s_pmask  = pm | (0xFFu << shift);
                    s_kk     = k - nxt;
                }
            }
        }
        __syncthreads();
    }

    // s_prefix == encoded k-th largest key (bit-exact); key >= thr matches
    // the reference's pred >= topkth comparison
    const unsigned thr = s_prefix;
    float* __restrict__ o = out + 2 + head * NROW + b * PER_B;
#pragma unroll
    for (int i = 0; i < KPT; i++)
        o[tid + SELT * i] = (key[i] >= thr) ? 1.0f : 0.0f;
}

// ---------------------------------------------------------------------------
extern "C" void kernel_launch(void* const* d_in, const int* in_sizes, int n_in,
                              void* d_out, int out_size)
{
    const float* table = (const float*)d_in[0];
    const int*   amask = (const int*)d_in[1];
    const int*   labS  = (const int*)d_in[2];
    const int*   labE  = (const int*)d_in[3];
    const float* W_S   = (const float*)d_in[4];
    const float* b_S   = (const float*)d_in[5];
    const float* W_E   = (const float*)d_in[6];
    const float* b_E   = (const float*)d_in[7];
    float* out = (float*)d_out;

    k_main<<<GRID1, 256>>>(table, W_S, W_E);

    // PDL: k_fuse launches while k_main drains; it self-synchronizes via
    // cudaGridDependencySynchronize() before reading k_main's outputs.
    cudaLaunchConfig_t cfg = {};
    cfg.gridDim  = dim3(256, 1, 1);
    cfg.blockDim = dim3(SELT, 1, 1);
    cudaLaunchAttribute attr[1];
    attr[0].id = cudaLaunchAttributeProgrammaticStreamSerialization;
    attr[0].val.programmaticStreamSerializationAllowed = 1;
    cfg.attrs = attr;
    cfg.numAttrs = 1;
    cudaLaunchKernelEx(&cfg, k_fuse, labS, labE, b_S, b_E, amask, out);
}

// round 16
// speedup vs baseline: 1.2201x; 1.0513x over previous
#include <cuda_runtime.h>
#include <cuda_bf16.h>

// Shapes fixed by setup_inputs
#define BATCH 8
#define L 128
#define D 768
#define NF4 (D / 4)                  // 192 float4 per row
#define NROW (BATCH * L * L)         // 131072
#define PER_B (L * L)                // 16384
#define NQUAD (NROW / 4)             // 32768
#define GRID1 592                    // 148 SMs x 4 blocks: exactly one wave
#define TOTW (GRID1 * 8)             // 4736 warps (quads/warp ~6.92, balanced)

// Device scratch (no allocations allowed)
__device__ float2   g_part[NROW * 8];   // per-(row, lane-group) partials, 8MB (L2-resident)
__device__ unsigned g_keyS[NROW];
__device__ unsigned g_keyE[NROW];
__device__ float    g_lpS[512];
__device__ float    g_lpE[512];
__device__ int      g_hist[16 * 256];   // per-(head,batch) top-byte histogram
__device__ unsigned g_cnt = 0;          // barrier arrival counter (self-resetting)
__device__ unsigned g_rel = 0;          // barrier generation (monotonic)

// order-preserving float->uint encoding (monotonic over all floats)
__device__ __forceinline__ unsigned enc_f32(float f)
{
    unsigned u = __float_as_uint(f);
    return (u & 0x80000000u) ? ~u : (u | 0x80000000u);
}

// Grid-wide generation barrier (validated in R13). All GRID1 blocks are
// co-resident (4 blocks/SM via __launch_bounds__(256,4)), so spinning is
// deadlock-free. Self-resetting across uses and graph replays.
__device__ __forceinline__ void grid_barrier()
{
    __syncthreads();
    if (threadIdx.x == 0) {
        __threadfence();                               // release my writes
        const unsigned gen = atomicAdd(&g_rel, 0u);    // read BEFORE arriving
        const unsigned old = atomicAdd(&g_cnt, 1u);
        if (old == GRID1 - 1u) {
            g_cnt = 0u;                                // reset before release
            __threadfence();
            atomicAdd(&g_rel, 1u);                     // release everyone
        } else {
            while (atomicAdd(&g_rel, 0u) == gen) { }
        }
    }
    __syncthreads();
    __threadfence();                                   // acquire
}

// ---------------------------------------------------------------------------
// K1: streaming dual GEMV (R10-proven mainloop) + grid barrier + phase A.
// Mainloop: warp covers 4 rows (8 lanes/row, 24 float4/lane); each lane
//   stores its own (sS,sE) partial as one 8B float2 (no cross-lane dep).
// Phase A (blocks 0-511, after barrier): 1 row/thread: reduce 8 lane
//   partials, bias, BCE partials + encoded keys; smem top-byte histogram
//   flushed sparsely to g_hist. Phase A carries no loop state -> mainloop
//   register allocation is unaffected (unlike the R13 mega-fusion).
// ---------------------------------------------------------------------------
__global__ __launch_bounds__(256, 4) void k_main(
    const float* __restrict__ table,
    const float* __restrict__ W_S, const float* __restrict__ W_E,
    const int* __restrict__ labS, const int* __restrict__ labE,
    const float* __restrict__ bSp, const float* __restrict__ bEp)
{
    __shared__ float4 sWs[NF4];
    __shared__ float4 sWe[NF4];
    __shared__ int    histS[256];
    __shared__ int    histE[256];
    __shared__ float  rS[8], rE[8];

    const int tid  = threadIdx.x;
    const int blk  = blockIdx.x;
    const int warp = tid >> 5;
    const int lane = tid & 31;

    if (blk < 16) g_hist[blk * 256 + tid] = 0;   // pre-barrier: safe

    for (int i = tid; i < NF4; i += 256) {
        sWs[i] = ((const float4*)W_S)[i];
        sWe[i] = ((const float4*)W_E)[i];
    }
    __syncthreads();

    // ======================= mainloop =======================
    {
        const int sub = lane >> 3;       // row within quad (0..3)
        const int o   = lane & 7;        // float4 base offset (0..7)
        const int gw  = blk * 8 + warp;

        for (int q = gw; q < NQUAD; q += TOTW) {
            const long long row = (long long)q * 4 + sub;
            const float4* __restrict__ t = (const float4*)table + row * NF4;

            float s0 = 0.f, s1 = 0.f, e0 = 0.f, e1 = 0.f;
#pragma unroll
            for (int j = 0; j < 24; j += 2) {
                const int i0 = o + 8 * j;
                const int i1 = i0 + 8;
                const float4 v0 = __ldcs(&t[i0]);
                const float4 v1 = __ldcs(&t[i1]);
                const float4 a0 = sWs[i0], b0 = sWe[i0];
                const float4 a1 = sWs[i1], b1 = sWe[i1];
                s0 += v0.x * a0.x + v0.y * a0.y + v0.z * a0.z + v0.w * a0.w;
                e0 += v0.x * b0.x + v0.y * b0.y + v0.z * b0.z + v0.w * b0.w;
                s1 += v1.x * a1.x + v1.y * a1.y + v1.z * a1.z + v1.w * a1.w;
                e1 += v1.x * b1.x + v1.y * b1.y + v1.z * b1.z + v1.w * b1.w;
            }
            g_part[row * 8 + o] = make_float2(s0 + s1, e0 + e1);
        }
    }

    grid_barrier();

    // ======================= Phase A: prep =======================
    if (blk < 512) {
        const int row = blk * 256 + tid;       // 1 row per thread
        const int b   = blk >> 6;              // batch (64 blocks each)

        histS[tid] = 0;
        histE[tid] = 0;
        __syncthreads();

        const float4* __restrict__ p = (const float4*)(g_part + (long long)row * 8);
        float sS = 0.f, sE = 0.f;
#pragma unroll
        for (int k = 0; k < 4; k++) {
            const float4 v = p[k];      // (sS, sE, sS, sE)
            sS += v.x + v.z;
            sE += v.y + v.w;
        }

        const float lS = sS + bSp[0];
        const float lE = sE + bEp[0];
        const int   tS = labS[row];
        const int   tE = labE[row];
        const float w  = (tS >= 0) ? 1.0f : 0.0f;

        float bceS = w * (fmaxf(lS, 0.f) - lS * (float)tS + __logf(1.f + __expf(-fabsf(lS))));
        float bceE = w * (fmaxf(lE, 0.f) - lE * (float)tE + __logf(1.f + __expf(-fabsf(lE))));

        const unsigned kS = enc_f32(w / (1.f + __expf(-lS)));
        const unsigned kE = enc_f32(w / (1.f + __expf(-lE)));
        g_keyS[row] = kS;
        g_keyE[row] = kE;
        atomicAdd(&histS[kS >> 24], 1);
        atomicAdd(&histE[kE >> 24], 1);

        // deterministic block loss partials
#pragma unroll
        for (int off = 16; off; off >>= 1) {
            bceS += __shfl_xor_sync(0xFFFFFFFFu, bceS, off);
            bceE += __shfl_xor_sync(0xFFFFFFFFu, bceE, off);
        }
        if (lane == 0) { rS[warp] = bceS; rE[warp] = bceE; }
        __syncthreads();
        if (tid == 0) {
            float a = 0.f, b2 = 0.f;
#pragma unroll
            for (int k = 0; k < 8; k++) { a += rS[k]; b2 += rE[k]; }
            g_lpS[blk] = a;
            g_lpE[blk] = b2;
        }

        // sparse flush: one REDG per nonzero bin (few dozen per block)
        const int cS = histS[tid];
        const int cE = histE[tid];
        if (cS) atomicAdd(&g_hist[b       * 256 + tid], cS);
        if (cE) atomicAdd(&g_hist[(8 + b) * 256 + tid], cE);
    }
}

// ---------------------------------------------------------------------------
// K2: blocks 0-15: exact k-th largest per (batch, head) — register key
// cache, pass-3 seeded from g_hist, sparse shared-atomic passes 2-0 —
// + predict-mask write. Block 16: final loss reduction (512 partials).
// out layout: [loss_S, loss_E, predict_S(131072), predict_E(131072)]
// ---------------------------------------------------------------------------
#define SELT 512
#define KPT  (PER_B / SELT)          // 32

__global__ __launch_bounds__(SELT) void k_sel(const int* __restrict__ amask,
                                              float* __restrict__ out)
{
    const int tid  = threadIdx.x;
    const int lane = tid & 31;
    const int warp = tid >> 5;

    if (blockIdx.x == 16) {
        __shared__ float sA[512], sB[512];
        sA[tid] = g_lpS[tid];
        sB[tid] = g_lpE[tid];
        __syncthreads();
        for (int s = 256; s; s >>= 1) {
            if (tid < s) { sA[tid] += sA[tid + s]; sB[tid] += sB[tid + s]; }
            __syncthreads();
        }
        if (tid == 0) {
            out[0] = sA[0] / (float)NROW;
            out[1] = sB[0] / (float)NROW;
        }
        return;
    }

    const int b    = blockIdx.x & 7;
    const int head = blockIdx.x >> 3;
    const int set  = head * 8 + b;
    const unsigned* __restrict__ keys = (head ? g_keyE : g_keyS) + b * PER_B;

    unsigned key[KPT];
#pragma unroll
    for (int i = 0; i < KPT; i++) key[i] = keys[tid + SELT * i];

    __shared__ int      s_suf[256];
    __shared__ int      s_kk;
    __shared__ unsigned s_prefix, s_pmask;

    // span-pruning k, computed by warp 0
    if (warp == 0) {
        int m = amask[b * L + lane] + amask[b * L + 32 + lane]
              + amask[b * L + 64 + lane] + amask[b * L + 96 + lane];
#pragma unroll
        for (int off = 16; off; off >>= 1) m += __shfl_xor_sync(0xFFFFFFFFu, m, off);
        if (lane == 0) {
            const int mlen = m - 2;
            int len = (int)((float)mlen * 0.3f);   // trunc like .astype(int32)
            if (len < 5) len = 5;
            const int mlsq = mlen * mlen;
            if (len > mlsq) len = mlsq;
            if (len < 1) len = 1;
            if (len > PER_B) len = PER_B;
            s_kk = len;
            s_prefix = 0u;
            s_pmask  = 0u;
        }
    }
    // pass-3 histogram precomputed in k_main phase A
    if (tid < 256) s_suf[tid] = g_hist[set * 256 + tid];
    __syncthreads();

    for (int pass = 3; pass >= 0; pass--) {
        const int shift = pass * 8;

        if (pass < 3) {
            if (tid < 256) s_suf[tid] = 0;
            __syncthreads();
            const unsigned pm = s_pmask;
            const unsigned pf = s_prefix;
#pragma unroll
            for (int i = 0; i < KPT; i++) {
                if ((key[i] & pm) == pf)
                    atomicAdd(&s_suf[(key[i] >> shift) & 0xFFu], 1);
            }
            __syncthreads();
        }

        // warp 0: suffix scan over 256 bins (8 bins/lane) + winner pick
        if (warp == 0) {
            const int k  = s_kk;
            const unsigned pf = s_prefix;
            const unsigned pm = s_pmask;
            int v[8], ls[8];
#pragma unroll
            for (int i = 0; i < 8; i++) v[i] = s_suf[lane * 8 + i];
            ls[7] = v[7];
#pragma unroll
            for (int i = 6; i >= 0; i--) ls[i] = ls[i + 1] + v[i];
            int T = ls[0];
            int S = T;
#pragma unroll
            for (int off = 1; off < 32; off <<= 1) {
                const int u = __shfl_down_sync(0xFFFFFFFFu, S, off);
                if (lane + off < 32) S += u;
            }
            const int E = S - T;   // sum over bins in higher lanes
#pragma unroll
            for (int i = 0; i < 8; i++) {
                const int suf = ls[i] + E;
                const int nxt = (i < 7) ? (ls[i + 1] + E) : E;
                if (suf >= k && nxt < k) {          // exactly one (lane,i) matches
                    s_prefix = pf | ((unsigned)(lane * 8 + i) << shift);
                    s_pmask  = pm | (0xFFu << shift);
                    s_kk     = k - nxt;
                }
            }
        }
        __syncthreads();
    }

    // s_prefix == encoded k-th largest key (bit-exact); key >= thr matches
    // the reference's pred >= topkth comparison
    const unsigned thr = s_prefix;
    float* __restrict__ o = out + 2 + head * NROW + b * PER_B;
#pragma unroll
    for (int i = 0; i < KPT; i++)
        o[tid + SELT * i] = (key[i] >= thr) ? 1.0f : 0.0f;
}

// ---------------------------------------------------------------------------
extern "C" void kernel_launch(void* const* d_in, const int* in_sizes, int n_in,
                              void* d_out, int out_size)
{
    const float* table = (const float*)d_in[0];
    const int*   amask = (const int*)d_in[1];
    const int*   labS  = (const int*)d_in[2];
    const int*   labE  = (const int*)d_in[3];
    const float* W_S   = (const float*)d_in[4];
    const float* b_S   = (const float*)d_in[5];
    const float* W_E   = (const float*)d_in[6];
    const float* b_E   = (const float*)d_in[7];
    float* out = (float*)d_out;

    k_main<<<GRID1, 256>>>(table, W_S, W_E, labS, labE, b_S, b_E);
    k_sel<<<17, SELT>>>(amask, out);
}

// round 17
// speedup vs baseline: 1.2256x; 1.0045x over previous
#include <cuda_runtime.h>
#include <cuda_bf16.h>

// Shapes fixed by setup_inputs
#define BATCH 8
#define L 128
#define D 768
#define NF4 (D / 4)                  // 192 float4 per row
#define NROW (BATCH * L * L)         // 131072
#define PER_B (L * L)                // 16384
#define NQUAD (NROW / 4)             // 32768
#define GRID1 592                    // 148 SMs x 4 blocks: exactly one wave
#define TOTW (GRID1 * 8)             // 4736 warps (quads/warp ~6.92, balanced)

// Device scratch (no allocations allowed)
__device__ float2   g_part[NROW * 8];   // per-(row, lane-group) partials, 8MB (L2-resident)
__device__ unsigned g_keyS[NROW];
__device__ unsigned g_keyE[NROW];
__device__ float    g_lpS[512];
__device__ float    g_lpE[512];
__device__ int      g_hist[16 * 256];   // per-(head,batch) top-byte histogram
__device__ int      g_kk[BATCH];        // per-batch span-pruning k
__device__ unsigned g_cnt = 0;          // barrier arrival counter (self-resetting)
__device__ unsigned g_rel = 0;          // barrier generation (monotonic)

// order-preserving float->uint encoding (monotonic over all floats)
__device__ __forceinline__ unsigned enc_f32(float f)
{
    unsigned u = __float_as_uint(f);
    return (u & 0x80000000u) ? ~u : (u | 0x80000000u);
}

// Grid-wide generation barrier (validated R13/R16). All GRID1 blocks are
// co-resident (4 blocks/SM via __launch_bounds__(256,4)), so spinning is
// deadlock-free. Self-resetting across uses and graph replays.
__device__ __forceinline__ void grid_barrier()
{
    __syncthreads();
    if (threadIdx.x == 0) {
        __threadfence();                               // release my writes
        const unsigned gen = atomicAdd(&g_rel, 0u);    // read BEFORE arriving
        const unsigned old = atomicAdd(&g_cnt, 1u);
        if (old == GRID1 - 1u) {
            g_cnt = 0u;                                // reset before release
            __threadfence();
            atomicAdd(&g_rel, 1u);                     // release everyone
        } else {
            while (atomicAdd(&g_rel, 0u) == gen) { }
        }
    }
    __syncthreads();
    __threadfence();                                   // acquire
}

// ---------------------------------------------------------------------------
// K1: streaming dual GEMV (proven mainloop) + grid barrier + phase A.
// Mainloop: warp covers 4 rows (8 lanes/row, 24 float4/lane); each lane
//   stores its own (sS,sE) partial as one 8B float2 (no cross-lane dep).
// Phase A (blocks 0-511, after barrier): 1 row/thread: reduce 8 lane
//   partials, bias, BCE partials + encoded keys; smem top-byte histogram
//   flushed sparsely to g_hist. Block 520 (idle otherwise) computes the
//   per-batch span-pruning k into g_kk.
// ---------------------------------------------------------------------------
__global__ __launch_bounds__(256, 4) void k_main(
    const float* __restrict__ table,
    const float* __restrict__ W_S, const float* __restrict__ W_E,
    const int* __restrict__ labS, const int* __restrict__ labE,
    const float* __restrict__ bSp, const float* __restrict__ bEp,
    const int* __restrict__ amask)
{
    __shared__ float4 sWs[NF4];
    __shared__ float4 sWe[NF4];
    __shared__ int    histS[256];
    __shared__ int    histE[256];
    __shared__ float  rS[8], rE[8];

    const int tid  = threadIdx.x;
    const int blk  = blockIdx.x;
    const int warp = tid >> 5;
    const int lane = tid & 31;

    if (blk < 16) g_hist[blk * 256 + tid] = 0;   // pre-barrier: safe

    for (int i = tid; i < NF4; i += 256) {
        sWs[i] = ((const float4*)W_S)[i];
        sWe[i] = ((const float4*)W_E)[i];
    }
    __syncthreads();

    // ======================= mainloop =======================
    {
        const int sub = lane >> 3;       // row within quad (0..3)
        const int o   = lane & 7;        // float4 base offset (0..7)
        const int gw  = blk * 8 + warp;

        for (int q = gw; q < NQUAD; q += TOTW) {
            const long long row = (long long)q * 4 + sub;
            const float4* __restrict__ t = (const float4*)table + row * NF4;

            float s0 = 0.f, s1 = 0.f, e0 = 0.f, e1 = 0.f;
#pragma unroll
            for (int j = 0; j < 24; j += 2) {
                const int i0 = o + 8 * j;
                const int i1 = i0 + 8;
                const float4 v0 = __ldcs(&t[i0]);
                const float4 v1 = __ldcs(&t[i1]);
                const float4 a0 = sWs[i0], b0 = sWe[i0];
                const float4 a1 = sWs[i1], b1 = sWe[i1];
                s0 += v0.x * a0.x + v0.y * a0.y + v0.z * a0.z + v0.w * a0.w;
                e0 += v0.x * b0.x + v0.y * b0.y + v0.z * b0.z + v0.w * b0.w;
                s1 += v1.x * a1.x + v1.y * a1.y + v1.z * a1.z + v1.w * a1.w;
                e1 += v1.x * b1.x + v1.y * b1.y + v1.z * b1.z + v1.w * b1.w;
            }
            g_part[row * 8 + o] = make_float2(s0 + s1, e0 + e1);
        }
    }

    grid_barrier();

    // ======================= Phase A: prep =======================
    if (blk < 512) {
        const int row = blk * 256 + tid;       // 1 row per thread
        const int b   = blk >> 6;              // batch (64 blocks each)

        histS[tid] = 0;
        histE[tid] = 0;
        __syncthreads();

        const float4* __restrict__ p = (const float4*)(g_part + (long long)row * 8);
        float sS = 0.f, sE = 0.f;
#pragma unroll
        for (int k = 0; k < 4; k++) {
            const float4 v = p[k];      // (sS, sE, sS, sE)
            sS += v.x + v.z;
            sE += v.y + v.w;
        }

        const float lS = sS + bSp[0];
        const float lE = sE + bEp[0];
        const int   tS = labS[row];
        const int   tE = labE[row];
        const float w  = (tS >= 0) ? 1.0f : 0.0f;

        float bceS = w * (fmaxf(lS, 0.f) - lS * (float)tS + __logf(1.f + __expf(-fabsf(lS))));
        float bceE = w * (fmaxf(lE, 0.f) - lE * (float)tE + __logf(1.f + __expf(-fabsf(lE))));

        const unsigned kS = enc_f32(w / (1.f + __expf(-lS)));
        const unsigned kE = enc_f32(w / (1.f + __expf(-lE)));
        g_keyS[row] = kS;
        g_keyE[row] = kE;
        atomicAdd(&histS[kS >> 24], 1);
        atomicAdd(&histE[kE >> 24], 1);

        // deterministic block loss partials
#pragma unroll
        for (int off = 16; off; off >>= 1) {
            bceS += __shfl_xor_sync(0xFFFFFFFFu, bceS, off);
            bceE += __shfl_xor_sync(0xFFFFFFFFu, bceE, off);
        }
        if (lane == 0) { rS[warp] = bceS; rE[warp] = bceE; }
        __syncthreads();
        if (tid == 0) {
            float a = 0.f, b2 = 0.f;
#pragma unroll
            for (int k = 0; k < 8; k++) { a += rS[k]; b2 += rE[k]; }
            g_lpS[blk] = a;
            g_lpE[blk] = b2;
        }

        // sparse flush: one REDG per nonzero bin (few dozen per block)
        const int cS = histS[tid];
        const int cE = histE[tid];
        if (cS) atomicAdd(&g_hist[b       * 256 + tid], cS);
        if (cE) atomicAdd(&g_hist[(8 + b) * 256 + tid], cE);
    } else if (blk == 520) {
        // per-batch span-pruning k (one warp per batch)
        if (warp < BATCH) {
            const int b = warp;
            int m = amask[b * L + lane] + amask[b * L + 32 + lane]
                  + amask[b * L + 64 + lane] + amask[b * L + 96 + lane];
#pragma unroll
            for (int off = 16; off; off >>= 1) m += __shfl_xor_sync(0xFFFFFFFFu, m, off);
            if (lane == 0) {
                const int mlen = m - 2;
                int len = (int)((float)mlen * 0.3f);   // trunc like .astype(int32)
                if (len < 5) len = 5;
                const int mlsq = mlen * mlen;
                if (len > mlsq) len = mlsq;
                if (len < 1) len = 1;
                if (len > PER_B) len = PER_B;
                g_kk[b] = len;
            }
        }
    }
}

// ---------------------------------------------------------------------------
// K2: blocks 0-15: exact k-th largest per (batch, head) — 1024 threads,
// 16 keys/thread in registers (short chains), pass-3 seeded from g_hist,
// sparse shared-atomic passes 2-0 — + predict-mask write.
// Block 16: final loss reduction (512 partials).
// out layout: [loss_S, loss_E, predict_S(131072), predict_E(131072)]
// ---------------------------------------------------------------------------
#define SELT 1024
#define KPT  (PER_B / SELT)          // 16

__global__ __launch_bounds__(SELT) void k_sel(float* __restrict__ out)
{
    const int tid  = threadIdx.x;
    const int lane = tid & 31;
    const int warp = tid >> 5;

    if (blockIdx.x == 16) {
        __shared__ float sA[512], sB[512];
        if (tid < 512) { sA[tid] = g_lpS[tid]; sB[tid] = g_lpE[tid]; }
        __syncthreads();
        for (int s = 256; s; s >>= 1) {
            if (tid < s) { sA[tid] += sA[tid + s]; sB[tid] += sB[tid + s]; }
            __syncthreads();
        }
        if (tid == 0) {
            out[0] = sA[0] / (float)NROW;
            out[1] = sB[0] / (float)NROW;
        }
        return;
    }

    const int b    = blockIdx.x & 7;
    const int head = blockIdx.x >> 3;
    const int set  = head * 8 + b;
    const unsigned* __restrict__ keys = (head ? g_keyE : g_keyS) + b * PER_B;

    unsigned key[KPT];
#pragma unroll
    for (int i = 0; i < KPT; i++) key[i] = keys[tid + SELT * i];

    __shared__ int      s_suf[256];
    __shared__ int      s_kk;
    __shared__ unsigned s_prefix, s_pmask;

    if (tid == 0) {
        s_kk     = g_kk[b];        // precomputed in k_main
        s_prefix = 0u;
        s_pmask  = 0u;
    }
    // pass-3 histogram precomputed in k_main phase A
    if (tid < 256) s_suf[tid] = g_hist[set * 256 + tid];
    __syncthreads();

    for (int pass = 3; pass >= 0; pass--) {
        const int shift = pass * 8;

        if (pass < 3) {
            if (tid < 256) s_suf[tid] = 0;
            __syncthreads();
            const unsigned pm = s_pmask;
            const unsigned pf = s_prefix;
#pragma unroll
            for (int i = 0; i < KPT; i++) {
                if ((key[i] & pm) == pf)
                    atomicAdd(&s_suf[(key[i] >> shift) & 0xFFu], 1);
            }
            __syncthreads();
        }

        // warp 0: suffix scan over 256 bins (8 bins/lane) + winner pick
        if (warp == 0) {
            const int k  = s_kk;
            const unsigned pf = s_prefix;
            const unsigned pm = s_pmask;
            int v[8], ls[8];
#pragma unroll
            for (int i = 0; i < 8; i++) v[i] = s_suf[lane * 8 + i];
            ls[7] = v[7];
#pragma unroll
            for (int i = 6; i >= 0; i--) ls[i] = ls[i + 1] + v[i];
            int T = ls[0];
            int S = T;
#pragma unroll
            for (int off = 1; off < 32; off <<= 1) {
                const int u = __shfl_down_sync(0xFFFFFFFFu, S, off);
                if (lane + off < 32) S += u;
            }
            const int E = S - T;   // sum over bins in higher lanes
#pragma unroll
            for (int i = 0; i < 8; i++) {
                const int suf = ls[i] + E;
                const int nxt = (i < 7) ? (ls[i + 1] + E) : E;
                if (suf >= k && nxt < k) {          // exactly one (lane,i) matches
                    s_prefix = pf | ((unsigned)(lane * 8 + i) << shift);
                    s_pmask  = pm | (0xFFu << shift);
                    s_kk     = k - nxt;
                }
            }
        }
        __syncthreads();
    }

    // s_prefix == encoded k-th largest key (bit-exact); key >= thr matches
    // the reference's pred >= topkth comparison
    const unsigned thr = s_prefix;
    float* __restrict__ o = out + 2 + head * NROW + b * PER_B;
#pragma unroll
    for (int i = 0; i < KPT; i++)
        o[tid + SELT * i] = (key[i] >= thr) ? 1.0f : 0.0f;
}

// ---------------------------------------------------------------------------
extern "C" void kernel_launch(void* const* d_in, const int* in_sizes, int n_in,
                              void* d_out, int out_size)
{
    const float* table = (const float*)d_in[0];
    const int*   amask = (const int*)d_in[1];
    const int*   labS  = (const int*)d_in[2];
    const int*   labE  = (const int*)d_in[3];
    const float* W_S   = (const float*)d_in[4];
    const float* b_S   = (const float*)d_in[5];
    const float* W_E   = (const float*)d_in[6];
    const float* b_E   = (const float*)d_in[7];
    float* out = (float*)d_out;

    k_main<<<GRID1, 256>>>(table, W_S, W_E, labS, labE, b_S, b_E, amask);
    k_sel<<<17, SELT>>>(out);
}